// round 5
// baseline (speedup 1.0000x reference)
#include <cuda_runtime.h>
#include <cuda_bf16.h>
#include <math.h>
#include <stdint.h>

#define BB 32
#define HH 512
#define VOCAB 50257
#define VPAD  50432          // multiple of 256
#define NB8   (VPAD/8)       // 6304 fragment columns
#define NBLK  (VPAD/256)     // 197 big-gemm blocks (256 cols each)
#define NBP   208            // padded partial stride

// ---------------- device scratch ----------------
__device__ float g_xcur[BB * HH];
__device__ float g_h0s[2][BB * HH];
__device__ float g_h1s[2][BB * HH];
__device__ float g_l0[BB * HH];
__device__ float g_x1[BB * HH];
__device__ uint4 g_Af[2 * 32 * 2 * 32];        // [hl][ks][m][lane]
__device__ uint4 g_Bf[(long)32 * NB8 * 32];    // [ks][n8][lane] -> {bh0,bh1,bl0,bl1} (103MB)
__device__ float g_c1p[VPAD];
__device__ float g_E[2][BB * VPAD];            // exp(logits), double buffered
__device__ float g_psum[BB * NBP];
__device__ float g_pmax[BB * NBP];
__device__ int   g_pidx[BB * NBP];
__device__ float g_invS[2][BB];                // double buffered

// ---------------- helpers ----------------
__device__ __forceinline__ uint32_t pk_bf2(float a, float b) {
    uint32_t ua = (uint32_t)__bfloat16_as_ushort(__float2bfloat16_rn(a));
    uint32_t ub = (uint32_t)__bfloat16_as_ushort(__float2bfloat16_rn(b));
    return ua | (ub << 16);
}
__device__ __forceinline__ float bf_hi(float v) {
    return __bfloat162float(__float2bfloat16_rn(v));
}
__device__ __forceinline__ void mma_bf16(float* d, const uint4& a, uint32_t b0, uint32_t b1) {
    asm volatile(
        "mma.sync.aligned.m16n8k16.row.col.f32.bf16.bf16.f32 "
        "{%0,%1,%2,%3},{%4,%5,%6,%7},{%8,%9},{%0,%1,%2,%3};\n"
        : "+f"(d[0]), "+f"(d[1]), "+f"(d[2]), "+f"(d[3])
        : "r"(a.x), "r"(a.y), "r"(a.z), "r"(a.w), "r"(b0), "r"(b1));
}

// ---------------- init ----------------
__global__ void k_init(const int* __restrict__ x, const float* __restrict__ h_prev,
                       const float* __restrict__ emb) {
    int b = blockIdx.x, j = threadIdx.x;
    g_xcur[b * HH + j]   = emb[(long)x[b] * HH + j];
    g_h0s[0][b * HH + j] = h_prev[b * HH + j];
    g_h1s[0][b * HH + j] = h_prev[b * HH + j];
}

__global__ void k_pack_c1(const float* __restrict__ c1) {
    int i = blockIdx.x * blockDim.x + threadIdx.x;
    if (i < VPAD) g_c1p[i] = (i < VOCAB) ? c1[i] : -1e30f;
}

// ---------------- pack V1 into bf16-split mma fragment layout ----------------
__global__ void k_pack_b(const float* __restrict__ V1) {
    __shared__ float sv[16][257];
    int bx = blockIdx.x, ks = blockIdx.y, tid = threadIdx.x;
    int cbase = bx * 256;
    #pragma unroll
    for (int r = 0; r < 16; r++) {
        int col = cbase + tid;
        int k = ks * 16 + r;
        sv[r][tid] = (col < VOCAB) ? V1[(long)k * VOCAB + col] : 0.0f;
    }
    __syncthreads();
    for (int e = tid; e < 1024; e += 256) {
        int lane = e & 31, n8l = e >> 5;
        int colL = n8l * 8 + (lane >> 2);
        int rr = (lane & 3) * 2;
        float v0 = sv[rr][colL],     v1 = sv[rr + 1][colL];
        float v8 = sv[rr + 8][colL], v9 = sv[rr + 9][colL];
        float h0 = bf_hi(v0), h1 = bf_hi(v1), h8 = bf_hi(v8), h9 = bf_hi(v9);
        uint4 o;
        o.x = pk_bf2(h0, h1);
        o.y = pk_bf2(h8, h9);
        o.z = pk_bf2(v0 - h0, v1 - h1);
        o.w = pk_bf2(v8 - h8, v9 - h9);
        g_Bf[((long)ks * NB8 + bx * 32 + n8l) * 32 + lane] = o;
    }
}

// ---------------- small GEMM core (shared by k_mat / k_cell1) ----------------
template<bool DUAL>
__device__ __forceinline__ float smallgemm_core(
        const float* __restrict__ A1, const float* __restrict__ A2,
        const float* __restrict__ W1, const float* __restrict__ W2,
        float* sA1, float* sA2, float* sW1, float* sW2,
        int jb, int jl, int r) {
    int tid = threadIdx.x;
    float a0 = 0.f, a1 = 0.f, a2 = 0.f, a3 = 0.f;
    for (int c = 0; c < 4; c++) {
        int k0 = c * 128;
        #pragma unroll
        for (int i = 0; i < 8; i++) {
            int idx = tid + i * 128;            // 0..1023
            int rr = idx >> 5, kk = idx & 31;
            *(float4*)(sA1 + rr * 132 + kk * 4) = *(const float4*)(A1 + rr * 512 + k0 + kk * 4);
            if (DUAL)
                *(float4*)(sA2 + rr * 132 + kk * 4) = *(const float4*)(A2 + rr * 512 + k0 + kk * 4);
        }
        #pragma unroll
        for (int i = 0; i < 4; i++) {
            int idx = tid + i * 128;            // 0..511
            int kk = idx >> 2, jj = idx & 3;
            sW1[jj * 132 + kk] = W1[(k0 + kk) * 512 + jb + jj];
            if (DUAL) sW2[jj * 132 + kk] = W2[(k0 + kk) * 512 + jb + jj];
        }
        __syncthreads();
        const float4* pa1 = (const float4*)(sA1 + r * 132);
        const float4* pw1 = (const float4*)(sW1 + jl * 132);
        #pragma unroll
        for (int k = 0; k < 32; k += 2) {
            float4 av = pa1[k],     wv = pw1[k];
            float4 bv = pa1[k + 1], xv = pw1[k + 1];
            a0 = fmaf(av.x, wv.x, a0); a0 = fmaf(av.y, wv.y, a0);
            a0 = fmaf(av.z, wv.z, a0); a0 = fmaf(av.w, wv.w, a0);
            a1 = fmaf(bv.x, xv.x, a1); a1 = fmaf(bv.y, xv.y, a1);
            a1 = fmaf(bv.z, xv.z, a1); a1 = fmaf(bv.w, xv.w, a1);
        }
        if (DUAL) {
            const float4* pa2 = (const float4*)(sA2 + r * 132);
            const float4* pw2 = (const float4*)(sW2 + jl * 132);
            #pragma unroll
            for (int k = 0; k < 32; k += 2) {
                float4 av = pa2[k],     wv = pw2[k];
                float4 bv = pa2[k + 1], xv = pw2[k + 1];
                a2 = fmaf(av.x, wv.x, a2); a2 = fmaf(av.y, wv.y, a2);
                a2 = fmaf(av.z, wv.z, a2); a2 = fmaf(av.w, wv.w, a2);
                a3 = fmaf(bv.x, xv.x, a3); a3 = fmaf(bv.y, xv.y, a3);
                a3 = fmaf(bv.z, xv.z, a3); a3 = fmaf(bv.w, xv.w, a3);
            }
        }
        __syncthreads();
    }
    return (a0 + a1) + (a2 + a3);
}

// out[32,512] = act(A1@W1 (+A2@W2) + bias). 128 blocks x 128 threads, 4 cols/block.
template<bool DUAL, bool TANH>
__global__ void __launch_bounds__(128) k_mat(
        const float* __restrict__ A1, const float* __restrict__ A2,
        const float* __restrict__ W1, const float* __restrict__ W2,
        const float* __restrict__ bias, float* __restrict__ out) {
    __shared__ float sA1[32 * 132];
    __shared__ float sA2[DUAL ? 32 * 132 : 4];
    __shared__ float sW1[4 * 132];
    __shared__ float sW2[DUAL ? 4 * 132 : 4];
    int tid = threadIdx.x;
    int jb = blockIdx.x * 4;
    int jl = tid & 3, r = tid >> 2;
    float acc = smallgemm_core<DUAL>(A1, A2, W1, W2, sA1, sA2, sW1, sW2, jb, jl, r);
    float o = acc + bias[jb + jl];
    if (TANH) o = tanhf(o);
    out[r * 512 + jb + jl] = o;
}

// layer-1 cell: h1 + out_h + A-fragment writes
__global__ void __launch_bounds__(128) k_cell1(
        const float* __restrict__ A1, const float* __restrict__ A2,
        const float* __restrict__ W1, const float* __restrict__ W2,
        const float* __restrict__ bias, float* __restrict__ h1out,
        float* __restrict__ out_h, int t, int T) {
    __shared__ float sA1[32 * 132];
    __shared__ float sA2[32 * 132];
    __shared__ float sW1[4 * 132];
    __shared__ float sW2[4 * 132];
    __shared__ float sH[32 * 5];
    int tid = threadIdx.x;
    int jb = blockIdx.x * 4;
    int jl = tid & 3, r = tid >> 2;
    float acc = smallgemm_core<true>(A1, A2, W1, W2, sA1, sA2, sW1, sW2, jb, jl, r);
    float o = tanhf(acc + bias[jb + jl]);
    h1out[r * 512 + jb + jl] = o;
    out_h[((long)r * T + t) * 512 + jb + jl] = o;
    sH[r * 5 + jl] = o;
    __syncthreads();

    // write the 128 A-fragment words this block owns (hi + lo planes)
    {
        int hl = tid >> 6, rem = tid & 63;
        int ps = rem & 1, rr = rem >> 1;
        int c0i = jb + ps * 2;
        float v0 = sH[rr * 5 + ps * 2], v1 = sH[rr * 5 + ps * 2 + 1];
        float h0f = bf_hi(v0), h1f = bf_hi(v1);
        uint32_t pk = hl ? pk_bf2(v0 - h0f, v1 - h1f) : pk_bf2(h0f, h1f);
        int ks = c0i >> 4, kk = c0i & 15;
        int hcol = (kk >> 3) & 1, g = (kk >> 1) & 3;
        int lane = (rr & 7) * 4 + g;
        int reg = hcol * 2 + ((rr >> 3) & 1);
        int mtile = rr >> 4;
        ((uint32_t*)g_Af)[(((hl * 32 + ks) * 2 + mtile) * 32 + lane) * 4 + reg] = pk;
    }
}

// ---------------- layer-0 softmax + tanh (warp-shuffle) ----------------
__global__ void __launch_bounds__(512) k_softmax_tanh(
        const float* __restrict__ logits, float* __restrict__ x1) {
    int b = blockIdx.x, tid = threadIdx.x;
    int wid = tid >> 5, lane = tid & 31;
    __shared__ float sred[16];
    __shared__ float sbcast;
    float l = logits[b * 512 + tid];

    float m = l;
    #pragma unroll
    for (int off = 16; off > 0; off >>= 1)
        m = fmaxf(m, __shfl_xor_sync(0xffffffffu, m, off));
    if (lane == 0) sred[wid] = m;
    __syncthreads();
    if (tid < 32) {
        float v = (tid < 16) ? sred[tid] : -3e38f;
        #pragma unroll
        for (int off = 8; off > 0; off >>= 1)
            v = fmaxf(v, __shfl_xor_sync(0xffffffffu, v, off));
        if (tid == 0) sbcast = v;
    }
    __syncthreads();
    float M = sbcast;
    float e = __expf(l - M);

    float s = e;
    #pragma unroll
    for (int off = 16; off > 0; off >>= 1)
        s += __shfl_xor_sync(0xffffffffu, s, off);
    if (lane == 0) sred[wid] = s;
    __syncthreads();
    if (tid < 32) {
        float v = (tid < 16) ? sred[tid] : 0.f;
        #pragma unroll
        for (int off = 8; off > 0; off >>= 1)
            v += __shfl_xor_sync(0xffffffffu, v, off);
        if (tid == 0) sbcast = v;
    }
    __syncthreads();
    x1[b * 512 + tid] = tanhf(e / sbcast);
}

// ---------------- big GEMM: 32 x VPAD via bf16-split mma + exp epilogue ----------------
__global__ void __launch_bounds__(256) k_big(int buf) {
    int tid = threadIdx.x, w = tid >> 5, lane = tid & 31;
    int bx = blockIdx.x;
    int n8base = bx * 32 + w * 4;
    float* Ebuf = g_E[buf];
    float acc[2][4][4];
    #pragma unroll
    for (int m = 0; m < 2; m++)
        #pragma unroll
        for (int n = 0; n < 4; n++)
            #pragma unroll
            for (int rr = 0; rr < 4; rr++) acc[m][n][rr] = 0.f;

    #pragma unroll 2
    for (int ks = 0; ks < 32; ks++) {
        uint4 ah0 = g_Af[(ks * 2 + 0) * 32 + lane];
        uint4 ah1 = g_Af[(ks * 2 + 1) * 32 + lane];
        uint4 al0 = g_Af[((32 + ks) * 2 + 0) * 32 + lane];
        uint4 al1 = g_Af[((32 + ks) * 2 + 1) * 32 + lane];
        uint4 bv[4];
        #pragma unroll
        for (int n = 0; n < 4; n++)
            bv[n] = g_Bf[((long)ks * NB8 + n8base + n) * 32 + lane];
        #pragma unroll
        for (int n = 0; n < 4; n++) {
            mma_bf16(acc[0][n], ah0, bv[n].x, bv[n].y);
            mma_bf16(acc[1][n], ah1, bv[n].x, bv[n].y);
            mma_bf16(acc[0][n], al0, bv[n].x, bv[n].y);
            mma_bf16(acc[1][n], al1, bv[n].x, bv[n].y);
            mma_bf16(acc[0][n], ah0, bv[n].z, bv[n].w);
            mma_bf16(acc[1][n], ah1, bv[n].z, bv[n].w);
        }
    }

    __shared__ float s_sum[8][32];
    __shared__ float s_max[8][32];
    __shared__ int   s_idx[8][32];
    int colw = bx * 256 + w * 32;
    float rsum[4] = {0.f, 0.f, 0.f, 0.f};
    float rmax[4] = {-3e38f, -3e38f, -3e38f, -3e38f};
    int   ridx[4] = {0, 0, 0, 0};

    #pragma unroll
    for (int m = 0; m < 2; m++) {
        #pragma unroll
        for (int n = 0; n < 4; n++) {
            int c0 = colw + n * 8 + ((lane & 3) << 1);
            float bias0 = g_c1p[c0], bias1 = g_c1p[c0 + 1];
            {
                float l0 = acc[m][n][0] + bias0, l1 = acc[m][n][1] + bias1;
                float e0 = __expf(l0), e1 = __expf(l1);
                int row = m * 16 + (lane >> 2);
                *(float2*)&Ebuf[(long)row * VPAD + c0] = make_float2(e0, e1);
                int slot = m * 2;
                rsum[slot] += e0 + e1;
                if (l0 > rmax[slot] || (l0 == rmax[slot] && c0 < ridx[slot])) { rmax[slot] = l0; ridx[slot] = c0; }
                if (l1 > rmax[slot] || (l1 == rmax[slot] && c0 + 1 < ridx[slot])) { rmax[slot] = l1; ridx[slot] = c0 + 1; }
            }
            {
                float l0 = acc[m][n][2] + bias0, l1 = acc[m][n][3] + bias1;
                float e0 = __expf(l0), e1 = __expf(l1);
                int row = m * 16 + (lane >> 2) + 8;
                *(float2*)&Ebuf[(long)row * VPAD + c0] = make_float2(e0, e1);
                int slot = m * 2 + 1;
                rsum[slot] += e0 + e1;
                if (l0 > rmax[slot] || (l0 == rmax[slot] && c0 < ridx[slot])) { rmax[slot] = l0; ridx[slot] = c0; }
                if (l1 > rmax[slot] || (l1 == rmax[slot] && c0 + 1 < ridx[slot])) { rmax[slot] = l1; ridx[slot] = c0 + 1; }
            }
        }
    }
    #pragma unroll
    for (int off = 1; off <= 2; off <<= 1) {
        #pragma unroll
        for (int slot = 0; slot < 4; slot++) {
            rsum[slot] += __shfl_xor_sync(0xffffffffu, rsum[slot], off);
            float v = __shfl_xor_sync(0xffffffffu, rmax[slot], off);
            int   i = __shfl_xor_sync(0xffffffffu, ridx[slot], off);
            if (v > rmax[slot] || (v == rmax[slot] && i < ridx[slot])) { rmax[slot] = v; ridx[slot] = i; }
        }
    }
    if ((lane & 3) == 0) {
        #pragma unroll
        for (int slot = 0; slot < 4; slot++) {
            int row = (slot >> 1) * 16 + (lane >> 2) + (slot & 1) * 8;
            s_sum[w][row] = rsum[slot];
            s_max[w][row] = rmax[slot];
            s_idx[w][row] = ridx[slot];
        }
    }
    __syncthreads();
    if (tid < 32) {
        int row = tid;
        float ps = 0.f, pv = -3e38f; int pi = 0;
        #pragma unroll
        for (int ww = 0; ww < 8; ww++) {
            ps += s_sum[ww][row];
            float v = s_max[ww][row]; int i = s_idx[ww][row];
            if (v > pv || (v == pv && i < pi)) { pv = v; pi = i; }
        }
        g_psum[row * NBP + bx] = ps;
        g_pmax[row * NBP + bx] = pv;
        g_pidx[row * NBP + bx] = pi;
    }
}

// ---------------- combine partials: invS + argmax + embed feedback ----------------
__global__ void k_comb(const float* __restrict__ emb, int buf) {
    __shared__ float rs[128], rv[128];
    __shared__ int   ri[128];
    int row = blockIdx.x, tid = threadIdx.x;
    float s = 0.f, mv = -3e38f; int mi = 0;
    for (int i = tid; i < NBLK; i += 128) {
        s += g_psum[row * NBP + i];
        float v = g_pmax[row * NBP + i]; int ix = g_pidx[row * NBP + i];
        if (v > mv || (v == mv && ix < mi)) { mv = v; mi = ix; }
    }
    rs[tid] = s; rv[tid] = mv; ri[tid] = mi;
    __syncthreads();
    for (int st = 64; st > 0; st >>= 1) {
        if (tid < st) {
            rs[tid] += rs[tid + st];
            float v = rv[tid + st]; int i = ri[tid + st];
            if (v > rv[tid] || (v == rv[tid] && i < ri[tid])) { rv[tid] = v; ri[tid] = i; }
        }
        __syncthreads();
    }
    if (tid == 0) g_invS[buf][row] = 1.0f / rs[0];
    int am = ri[0];
    for (int j = tid; j < 512; j += 128)
        g_xcur[row * 512 + j] = emb[(long)am * 512 + j];
}

// ---------------- write y (runs on side stream) ----------------
__global__ void k_writey(float* __restrict__ out_y, int t, int T, int buf) {
    int b = blockIdx.y;
    float inv = g_invS[buf][b];
    const float* erow = &g_E[buf][(long)b * VPAD];
    float* yrow = &out_y[((long)b * T + t) * VOCAB];
    for (int j = blockIdx.x * blockDim.x + threadIdx.x; j < VOCAB; j += gridDim.x * blockDim.x)
        yrow[j] = erow[j] * inv;
}

// ---------------- host launcher ----------------
extern "C" void kernel_launch(void* const* d_in, const int* in_sizes, int n_in,
                              void* d_out, int out_size) {
    const int*   x      = (const int*)d_in[0];
    const float* h_prev = (const float*)d_in[3];
    const float* emb    = (const float*)d_in[4];
    const float* U0     = (const float*)d_in[5];
    const float* W0     = (const float*)d_in[6];
    const float* b0     = (const float*)d_in[7];
    const float* V0     = (const float*)d_in[8];
    const float* c0     = (const float*)d_in[9];
    const float* U1     = (const float*)d_in[10];
    const float* W1     = (const float*)d_in[11];
    const float* b1     = (const float*)d_in[12];
    const float* V1     = (const float*)d_in[13];
    const float* c1     = (const float*)d_in[14];

    float* out = (float*)d_out;
    int T = out_size / (BB * (HH + VOCAB));
    float* out_h = out;
    float* out_y = out + (long)BB * T * HH;

    float *p_xcur, *p_h0, *p_h1, *p_l0, *p_x1;
    cudaGetSymbolAddress((void**)&p_xcur, g_xcur);
    cudaGetSymbolAddress((void**)&p_h0,   g_h0s);
    cudaGetSymbolAddress((void**)&p_h1,   g_h1s);
    cudaGetSymbolAddress((void**)&p_l0,   g_l0);
    cudaGetSymbolAddress((void**)&p_x1,   g_x1);

    // one-time side stream + events (host-side objects only; no device memory)
    static cudaStream_t s2 = nullptr;
    static cudaEvent_t evC = nullptr, evW[2] = {nullptr, nullptr};
    if (!s2) {
        cudaStreamCreateWithFlags(&s2, cudaStreamNonBlocking);
        cudaEventCreateWithFlags(&evC, cudaEventDisableTiming);
        cudaEventCreateWithFlags(&evW[0], cudaEventDisableTiming);
        cudaEventCreateWithFlags(&evW[1], cudaEventDisableTiming);
    }

    k_init<<<BB, 512>>>(x, h_prev, emb);
    k_pack_c1<<<(VPAD + 255) / 256, 256>>>(c1);
    k_pack_b<<<dim3(197, 32), 256>>>(V1);

    for (int t = 0; t < T; t++) {
        int cur = t & 1;
        float* h0c = p_h0 + cur * BB * HH;
        float* h0n = p_h0 + (cur ^ 1) * BB * HH;
        float* h1c = p_h1 + cur * BB * HH;
        float* h1n = p_h1 + (cur ^ 1) * BB * HH;

        k_mat<true, true><<<128, 128>>>(p_xcur, h0c, U0, W0, b0, h0n);
        k_mat<false, false><<<128, 128>>>(h0n, nullptr, V0, nullptr, c0, p_l0);
        k_softmax_tanh<<<BB, 512>>>(p_l0, p_x1);
        k_cell1<<<128, 128>>>(p_x1, h1c, U1, W1, b1, h1n, out_h, t, T);

        // k_big(t) reuses E buffer of step t-2: wait for that writey first
        if (t >= 2) cudaStreamWaitEvent(0, evW[cur], 0);
        k_big<<<NBLK, 256>>>(cur);
        k_comb<<<BB, 128>>>(emb, cur);

        // fork: y-write overlaps the next step on side stream
        cudaEventRecord(evC, 0);
        cudaStreamWaitEvent(s2, evC, 0);
        k_writey<<<dim3(64, BB), 256, 0, s2>>>(out_y, t, T, cur);
        cudaEventRecord(evW[cur], s2);
    }
    // join side stream back before returning
    if (T >= 1) cudaStreamWaitEvent(0, evW[(T - 1) & 1], 0);
    if (T >= 2) cudaStreamWaitEvent(0, evW[T & 1], 0);
}

// round 6
// speedup vs baseline: 1.0051x; 1.0051x over previous
#include <cuda_runtime.h>
#include <cuda_bf16.h>
#include <math.h>
#include <stdint.h>

#define BB 32
#define HH 512
#define VOCAB 50257
#define VPAD  50432          // multiple of 256
#define NB8   (VPAD/8)       // 6304 fragment columns
#define NBLK  (VPAD/256)     // 197 big-gemm blocks (256 cols each)
#define NBP   208            // padded partial stride

// ---------------- device scratch ----------------
__device__ float g_xcur[BB * HH];
__device__ float g_h0s[2][BB * HH];
__device__ float g_h1s[2][BB * HH];
__device__ float g_l0[BB * HH];
__device__ float g_x1[BB * HH];
__device__ uint4 g_Af[2 * 32 * 2 * 32];        // [hl][ks][m][lane]
__device__ uint4 g_Bf[(long)32 * NB8 * 32];    // [ks][n8][lane] -> {bh0,bh1,bl0,bl1} (103MB)
__device__ float g_c1p[VPAD];
__device__ float g_E[2][BB * VPAD];            // exp(logits), double buffered
__device__ float g_psum[BB * NBP];
__device__ float g_pmax[BB * NBP];
__device__ int   g_pidx[BB * NBP];
__device__ float g_invS[2][BB];                // double buffered

// ---------------- helpers ----------------
__device__ __forceinline__ uint32_t pk_bf2(float a, float b) {
    uint32_t ua = (uint32_t)__bfloat16_as_ushort(__float2bfloat16_rn(a));
    uint32_t ub = (uint32_t)__bfloat16_as_ushort(__float2bfloat16_rn(b));
    return ua | (ub << 16);
}
__device__ __forceinline__ float bf_hi(float v) {
    return __bfloat162float(__float2bfloat16_rn(v));
}
__device__ __forceinline__ void mma_bf16(float* d, const uint4& a, uint32_t b0, uint32_t b1) {
    asm volatile(
        "mma.sync.aligned.m16n8k16.row.col.f32.bf16.bf16.f32 "
        "{%0,%1,%2,%3},{%4,%5,%6,%7},{%8,%9},{%0,%1,%2,%3};\n"
        : "+f"(d[0]), "+f"(d[1]), "+f"(d[2]), "+f"(d[3])
        : "r"(a.x), "r"(a.y), "r"(a.z), "r"(a.w), "r"(b0), "r"(b1));
}

// ---------------- init ----------------
__global__ void k_init(const int* __restrict__ x, const float* __restrict__ h_prev,
                       const float* __restrict__ emb) {
    int b = blockIdx.x, j = threadIdx.x;
    g_xcur[b * HH + j]   = emb[(long)x[b] * HH + j];
    g_h0s[0][b * HH + j] = h_prev[b * HH + j];
    g_h1s[0][b * HH + j] = h_prev[b * HH + j];
}

__global__ void k_pack_c1(const float* __restrict__ c1) {
    int i = blockIdx.x * blockDim.x + threadIdx.x;
    if (i < VPAD) g_c1p[i] = (i < VOCAB) ? c1[i] : -1e30f;
}

// ---------------- pack V1 into bf16-split mma fragment layout ----------------
__global__ void k_pack_b(const float* __restrict__ V1) {
    __shared__ float sv[16][257];
    int bx = blockIdx.x, ks = blockIdx.y, tid = threadIdx.x;
    int cbase = bx * 256;
    #pragma unroll
    for (int r = 0; r < 16; r++) {
        int col = cbase + tid;
        int k = ks * 16 + r;
        sv[r][tid] = (col < VOCAB) ? V1[(long)k * VOCAB + col] : 0.0f;
    }
    __syncthreads();
    for (int e = tid; e < 1024; e += 256) {
        int lane = e & 31, n8l = e >> 5;
        int colL = n8l * 8 + (lane >> 2);
        int rr = (lane & 3) * 2;
        float v0 = sv[rr][colL],     v1 = sv[rr + 1][colL];
        float v8 = sv[rr + 8][colL], v9 = sv[rr + 9][colL];
        float h0 = bf_hi(v0), h1 = bf_hi(v1), h8 = bf_hi(v8), h9 = bf_hi(v9);
        uint4 o;
        o.x = pk_bf2(h0, h1);
        o.y = pk_bf2(h8, h9);
        o.z = pk_bf2(v0 - h0, v1 - h1);
        o.w = pk_bf2(v8 - h8, v9 - h9);
        g_Bf[((long)ks * NB8 + bx * 32 + n8l) * 32 + lane] = o;
    }
}

// ---------------- small GEMM core (shared by k_mat / k_cell1) ----------------
template<bool DUAL>
__device__ __forceinline__ float smallgemm_core(
        const float* __restrict__ A1, const float* __restrict__ A2,
        const float* __restrict__ W1, const float* __restrict__ W2,
        float* sA1, float* sA2, float* sW1, float* sW2,
        int jb, int jl, int r) {
    int tid = threadIdx.x;
    float a0 = 0.f, a1 = 0.f, a2 = 0.f, a3 = 0.f;
    for (int c = 0; c < 4; c++) {
        int k0 = c * 128;
        #pragma unroll
        for (int i = 0; i < 8; i++) {
            int idx = tid + i * 128;            // 0..1023
            int rr = idx >> 5, kk = idx & 31;
            *(float4*)(sA1 + rr * 132 + kk * 4) = *(const float4*)(A1 + rr * 512 + k0 + kk * 4);
            if (DUAL)
                *(float4*)(sA2 + rr * 132 + kk * 4) = *(const float4*)(A2 + rr * 512 + k0 + kk * 4);
        }
        #pragma unroll
        for (int i = 0; i < 4; i++) {
            int idx = tid + i * 128;            // 0..511
            int kk = idx >> 2, jj = idx & 3;
            sW1[jj * 132 + kk] = W1[(k0 + kk) * 512 + jb + jj];
            if (DUAL) sW2[jj * 132 + kk] = W2[(k0 + kk) * 512 + jb + jj];
        }
        __syncthreads();
        const float4* pa1 = (const float4*)(sA1 + r * 132);
        const float4* pw1 = (const float4*)(sW1 + jl * 132);
        #pragma unroll
        for (int k = 0; k < 32; k += 2) {
            float4 av = pa1[k],     wv = pw1[k];
            float4 bv = pa1[k + 1], xv = pw1[k + 1];
            a0 = fmaf(av.x, wv.x, a0); a0 = fmaf(av.y, wv.y, a0);
            a0 = fmaf(av.z, wv.z, a0); a0 = fmaf(av.w, wv.w, a0);
            a1 = fmaf(bv.x, xv.x, a1); a1 = fmaf(bv.y, xv.y, a1);
            a1 = fmaf(bv.z, xv.z, a1); a1 = fmaf(bv.w, xv.w, a1);
        }
        if (DUAL) {
            const float4* pa2 = (const float4*)(sA2 + r * 132);
            const float4* pw2 = (const float4*)(sW2 + jl * 132);
            #pragma unroll
            for (int k = 0; k < 32; k += 2) {
                float4 av = pa2[k],     wv = pw2[k];
                float4 bv = pa2[k + 1], xv = pw2[k + 1];
                a2 = fmaf(av.x, wv.x, a2); a2 = fmaf(av.y, wv.y, a2);
                a2 = fmaf(av.z, wv.z, a2); a2 = fmaf(av.w, wv.w, a2);
                a3 = fmaf(bv.x, xv.x, a3); a3 = fmaf(bv.y, xv.y, a3);
                a3 = fmaf(bv.z, xv.z, a3); a3 = fmaf(bv.w, xv.w, a3);
            }
        }
        __syncthreads();
    }
    return (a0 + a1) + (a2 + a3);
}

// out[32,512] = act(A1@W1 (+A2@W2) + bias). 128 blocks x 128 threads, 4 cols/block.
template<bool DUAL, bool TANH>
__global__ void __launch_bounds__(128) k_mat(
        const float* __restrict__ A1, const float* __restrict__ A2,
        const float* __restrict__ W1, const float* __restrict__ W2,
        const float* __restrict__ bias, float* __restrict__ out) {
    __shared__ float sA1[32 * 132];
    __shared__ float sA2[DUAL ? 32 * 132 : 4];
    __shared__ float sW1[4 * 132];
    __shared__ float sW2[DUAL ? 4 * 132 : 4];
    int tid = threadIdx.x;
    int jb = blockIdx.x * 4;
    int jl = tid & 3, r = tid >> 2;
    float acc = smallgemm_core<DUAL>(A1, A2, W1, W2, sA1, sA2, sW1, sW2, jb, jl, r);
    float o = acc + bias[jb + jl];
    if (TANH) o = tanhf(o);
    out[r * 512 + jb + jl] = o;
}

// layer-1 cell: h1 + out_h + A-fragment writes
__global__ void __launch_bounds__(128) k_cell1(
        const float* __restrict__ A1, const float* __restrict__ A2,
        const float* __restrict__ W1, const float* __restrict__ W2,
        const float* __restrict__ bias, float* __restrict__ h1out,
        float* __restrict__ out_h, int t, int T) {
    __shared__ float sA1[32 * 132];
    __shared__ float sA2[32 * 132];
    __shared__ float sW1[4 * 132];
    __shared__ float sW2[4 * 132];
    __shared__ float sH[32 * 5];
    int tid = threadIdx.x;
    int jb = blockIdx.x * 4;
    int jl = tid & 3, r = tid >> 2;
    float acc = smallgemm_core<true>(A1, A2, W1, W2, sA1, sA2, sW1, sW2, jb, jl, r);
    float o = tanhf(acc + bias[jb + jl]);
    h1out[r * 512 + jb + jl] = o;
    out_h[((long)r * T + t) * 512 + jb + jl] = o;
    sH[r * 5 + jl] = o;
    __syncthreads();

    // write the 128 A-fragment words this block owns (hi + lo planes)
    {
        int hl = tid >> 6, rem = tid & 63;
        int ps = rem & 1, rr = rem >> 1;
        int c0i = jb + ps * 2;
        float v0 = sH[rr * 5 + ps * 2], v1 = sH[rr * 5 + ps * 2 + 1];
        float h0f = bf_hi(v0), h1f = bf_hi(v1);
        uint32_t pk = hl ? pk_bf2(v0 - h0f, v1 - h1f) : pk_bf2(h0f, h1f);
        int ks = c0i >> 4, kk = c0i & 15;
        int hcol = (kk >> 3) & 1, g = (kk >> 1) & 3;
        int lane = (rr & 7) * 4 + g;
        int reg = hcol * 2 + ((rr >> 3) & 1);
        int mtile = rr >> 4;
        ((uint32_t*)g_Af)[(((hl * 32 + ks) * 2 + mtile) * 32 + lane) * 4 + reg] = pk;
    }
}

// ---------------- layer-0 softmax + tanh (warp-shuffle) ----------------
__global__ void __launch_bounds__(512) k_softmax_tanh(
        const float* __restrict__ logits, float* __restrict__ x1) {
    int b = blockIdx.x, tid = threadIdx.x;
    int wid = tid >> 5, lane = tid & 31;
    __shared__ float sred[16];
    __shared__ float sbcast;
    float l = logits[b * 512 + tid];

    float m = l;
    #pragma unroll
    for (int off = 16; off > 0; off >>= 1)
        m = fmaxf(m, __shfl_xor_sync(0xffffffffu, m, off));
    if (lane == 0) sred[wid] = m;
    __syncthreads();
    if (tid < 32) {
        float v = (tid < 16) ? sred[tid] : -3e38f;
        #pragma unroll
        for (int off = 8; off > 0; off >>= 1)
            v = fmaxf(v, __shfl_xor_sync(0xffffffffu, v, off));
        if (tid == 0) sbcast = v;
    }
    __syncthreads();
    float M = sbcast;
    float e = __expf(l - M);

    float s = e;
    #pragma unroll
    for (int off = 16; off > 0; off >>= 1)
        s += __shfl_xor_sync(0xffffffffu, s, off);
    if (lane == 0) sred[wid] = s;
    __syncthreads();
    if (tid < 32) {
        float v = (tid < 16) ? sred[tid] : 0.f;
        #pragma unroll
        for (int off = 8; off > 0; off >>= 1)
            v += __shfl_xor_sync(0xffffffffu, v, off);
        if (tid == 0) sbcast = v;
    }
    __syncthreads();
    x1[b * 512 + tid] = tanhf(e / sbcast);
}

// ---------------- big GEMM: 32 x VPAD via bf16-split mma + exp epilogue ----------------
__global__ void __launch_bounds__(256) k_big(int buf) {
    int tid = threadIdx.x, w = tid >> 5, lane = tid & 31;
    int bx = blockIdx.x;
    int n8base = bx * 32 + w * 4;
    float* Ebuf = g_E[buf];
    float acc[2][4][4];
    #pragma unroll
    for (int m = 0; m < 2; m++)
        #pragma unroll
        for (int n = 0; n < 4; n++)
            #pragma unroll
            for (int rr = 0; rr < 4; rr++) acc[m][n][rr] = 0.f;

    #pragma unroll 2
    for (int ks = 0; ks < 32; ks++) {
        uint4 ah0 = g_Af[(ks * 2 + 0) * 32 + lane];
        uint4 ah1 = g_Af[(ks * 2 + 1) * 32 + lane];
        uint4 al0 = g_Af[((32 + ks) * 2 + 0) * 32 + lane];
        uint4 al1 = g_Af[((32 + ks) * 2 + 1) * 32 + lane];
        uint4 bv[4];
        #pragma unroll
        for (int n = 0; n < 4; n++)
            bv[n] = g_Bf[((long)ks * NB8 + n8base + n) * 32 + lane];
        #pragma unroll
        for (int n = 0; n < 4; n++) {
            mma_bf16(acc[0][n], ah0, bv[n].x, bv[n].y);
            mma_bf16(acc[1][n], ah1, bv[n].x, bv[n].y);
            mma_bf16(acc[0][n], al0, bv[n].x, bv[n].y);
            mma_bf16(acc[1][n], al1, bv[n].x, bv[n].y);
            mma_bf16(acc[0][n], ah0, bv[n].z, bv[n].w);
            mma_bf16(acc[1][n], ah1, bv[n].z, bv[n].w);
        }
    }

    __shared__ float s_sum[8][32];
    __shared__ float s_max[8][32];
    __shared__ int   s_idx[8][32];
    int colw = bx * 256 + w * 32;
    float rsum[4] = {0.f, 0.f, 0.f, 0.f};
    float rmax[4] = {-3e38f, -3e38f, -3e38f, -3e38f};
    int   ridx[4] = {0, 0, 0, 0};

    #pragma unroll
    for (int m = 0; m < 2; m++) {
        #pragma unroll
        for (int n = 0; n < 4; n++) {
            int c0 = colw + n * 8 + ((lane & 3) << 1);
            float bias0 = g_c1p[c0], bias1 = g_c1p[c0 + 1];
            {
                float l0 = acc[m][n][0] + bias0, l1 = acc[m][n][1] + bias1;
                float e0 = __expf(l0), e1 = __expf(l1);
                int row = m * 16 + (lane >> 2);
                *(float2*)&Ebuf[(long)row * VPAD + c0] = make_float2(e0, e1);
                int slot = m * 2;
                rsum[slot] += e0 + e1;
                if (l0 > rmax[slot] || (l0 == rmax[slot] && c0 < ridx[slot])) { rmax[slot] = l0; ridx[slot] = c0; }
                if (l1 > rmax[slot] || (l1 == rmax[slot] && c0 + 1 < ridx[slot])) { rmax[slot] = l1; ridx[slot] = c0 + 1; }
            }
            {
                float l0 = acc[m][n][2] + bias0, l1 = acc[m][n][3] + bias1;
                float e0 = __expf(l0), e1 = __expf(l1);
                int row = m * 16 + (lane >> 2) + 8;
                *(float2*)&Ebuf[(long)row * VPAD + c0] = make_float2(e0, e1);
                int slot = m * 2 + 1;
                rsum[slot] += e0 + e1;
                if (l0 > rmax[slot] || (l0 == rmax[slot] && c0 < ridx[slot])) { rmax[slot] = l0; ridx[slot] = c0; }
                if (l1 > rmax[slot] || (l1 == rmax[slot] && c0 + 1 < ridx[slot])) { rmax[slot] = l1; ridx[slot] = c0 + 1; }
            }
        }
    }
    #pragma unroll
    for (int off = 1; off <= 2; off <<= 1) {
        #pragma unroll
        for (int slot = 0; slot < 4; slot++) {
            rsum[slot] += __shfl_xor_sync(0xffffffffu, rsum[slot], off);
            float v = __shfl_xor_sync(0xffffffffu, rmax[slot], off);
            int   i = __shfl_xor_sync(0xffffffffu, ridx[slot], off);
            if (v > rmax[slot] || (v == rmax[slot] && i < ridx[slot])) { rmax[slot] = v; ridx[slot] = i; }
        }
    }
    if ((lane & 3) == 0) {
        #pragma unroll
        for (int slot = 0; slot < 4; slot++) {
            int row = (slot >> 1) * 16 + (lane >> 2) + (slot & 1) * 8;
            s_sum[w][row] = rsum[slot];
            s_max[w][row] = rmax[slot];
            s_idx[w][row] = ridx[slot];
        }
    }
    __syncthreads();
    if (tid < 32) {
        int row = tid;
        float ps = 0.f, pv = -3e38f; int pi = 0;
        #pragma unroll
        for (int ww = 0; ww < 8; ww++) {
            ps += s_sum[ww][row];
            float v = s_max[ww][row]; int i = s_idx[ww][row];
            if (v > pv || (v == pv && i < pi)) { pv = v; pi = i; }
        }
        g_psum[row * NBP + bx] = ps;
        g_pmax[row * NBP + bx] = pv;
        g_pidx[row * NBP + bx] = pi;
    }
}

// ---------------- combine partials: invS + argmax + embed feedback ----------------
__global__ void k_comb(const float* __restrict__ emb, int buf) {
    __shared__ float rs[128], rv[128];
    __shared__ int   ri[128];
    int row = blockIdx.x, tid = threadIdx.x;
    float s = 0.f, mv = -3e38f; int mi = 0;
    for (int i = tid; i < NBLK; i += 128) {
        s += g_psum[row * NBP + i];
        float v = g_pmax[row * NBP + i]; int ix = g_pidx[row * NBP + i];
        if (v > mv || (v == mv && ix < mi)) { mv = v; mi = ix; }
    }
    rs[tid] = s; rv[tid] = mv; ri[tid] = mi;
    __syncthreads();
    for (int st = 64; st > 0; st >>= 1) {
        if (tid < st) {
            rs[tid] += rs[tid + st];
            float v = rv[tid + st]; int i = ri[tid + st];
            if (v > rv[tid] || (v == rv[tid] && i < ri[tid])) { rv[tid] = v; ri[tid] = i; }
        }
        __syncthreads();
    }
    if (tid == 0) g_invS[buf][row] = 1.0f / rs[0];
    int am = ri[0];
    for (int j = tid; j < 512; j += 128)
        g_xcur[row * 512 + j] = emb[(long)am * 512 + j];
}

// ---------------- write y (runs on side stream) ----------------
__global__ void k_writey(float* __restrict__ out_y, int t, int T, int buf) {
    int b = blockIdx.y;
    float inv = g_invS[buf][b];
    const float* erow = &g_E[buf][(long)b * VPAD];
    float* yrow = &out_y[((long)b * T + t) * VOCAB];
    for (int j = blockIdx.x * blockDim.x + threadIdx.x; j < VOCAB; j += gridDim.x * blockDim.x)
        yrow[j] = erow[j] * inv;
}

// ---------------- host launcher ----------------
extern "C" void kernel_launch(void* const* d_in, const int* in_sizes, int n_in,
                              void* d_out, int out_size) {
    const int*   x      = (const int*)d_in[0];
    const float* h_prev = (const float*)d_in[3];
    const float* emb    = (const float*)d_in[4];
    const float* U0     = (const float*)d_in[5];
    const float* W0     = (const float*)d_in[6];
    const float* b0     = (const float*)d_in[7];
    const float* V0     = (const float*)d_in[8];
    const float* c0     = (const float*)d_in[9];
    const float* U1     = (const float*)d_in[10];
    const float* W1     = (const float*)d_in[11];
    const float* b1     = (const float*)d_in[12];
    const float* V1     = (const float*)d_in[13];
    const float* c1     = (const float*)d_in[14];

    float* out = (float*)d_out;
    int T = out_size / (BB * (HH + VOCAB));
    float* out_h = out;
    float* out_y = out + (long)BB * T * HH;

    float *p_xcur, *p_h0, *p_h1, *p_l0, *p_x1;
    cudaGetSymbolAddress((void**)&p_xcur, g_xcur);
    cudaGetSymbolAddress((void**)&p_h0,   g_h0s);
    cudaGetSymbolAddress((void**)&p_h1,   g_h1s);
    cudaGetSymbolAddress((void**)&p_l0,   g_l0);
    cudaGetSymbolAddress((void**)&p_x1,   g_x1);

    // one-time side stream + events (host-side objects only; no device memory)
    static cudaStream_t s2 = nullptr;
    static cudaEvent_t evC = nullptr, evW[2] = {nullptr, nullptr};
    if (!s2) {
        cudaStreamCreateWithFlags(&s2, cudaStreamNonBlocking);
        cudaEventCreateWithFlags(&evC, cudaEventDisableTiming);
        cudaEventCreateWithFlags(&evW[0], cudaEventDisableTiming);
        cudaEventCreateWithFlags(&evW[1], cudaEventDisableTiming);
    }

    k_init<<<BB, 512>>>(x, h_prev, emb);
    k_pack_c1<<<(VPAD + 255) / 256, 256>>>(c1);
    k_pack_b<<<dim3(197, 32), 256>>>(V1);

    for (int t = 0; t < T; t++) {
        int cur = t & 1;
        float* h0c = p_h0 + cur * BB * HH;
        float* h0n = p_h0 + (cur ^ 1) * BB * HH;
        float* h1c = p_h1 + cur * BB * HH;
        float* h1n = p_h1 + (cur ^ 1) * BB * HH;

        k_mat<true, true><<<128, 128>>>(p_xcur, h0c, U0, W0, b0, h0n);
        k_mat<false, false><<<128, 128>>>(h0n, nullptr, V0, nullptr, c0, p_l0);
        k_softmax_tanh<<<BB, 512>>>(p_l0, p_x1);
        k_cell1<<<128, 128>>>(p_x1, h1c, U1, W1, b1, h1n, out_h, t, T);

        // k_big(t) reuses E buffer of step t-2: wait for that writey first
        if (t >= 2) cudaStreamWaitEvent(0, evW[cur], 0);
        k_big<<<NBLK, 256>>>(cur);
        k_comb<<<BB, 128>>>(emb, cur);

        // fork: y-write overlaps the next step on side stream
        cudaEventRecord(evC, 0);
        cudaStreamWaitEvent(s2, evC, 0);
        k_writey<<<dim3(64, BB), 256, 0, s2>>>(out_y, t, T, cur);
        cudaEventRecord(evW[cur], s2);
    }
    // join side stream back before returning
    if (T >= 1) cudaStreamWaitEvent(0, evW[(T - 1) & 1], 0);
    if (T >= 2) cudaStreamWaitEvent(0, evW[T & 1], 0);
}